// round 1
// baseline (speedup 1.0000x reference)
#include <cuda_runtime.h>
#include <cuda_bf16.h>
#include <math.h>

// Problem constants
#define Bb 2
#define Ss 2048
#define Dd 1024
#define Hh 16
#define Kk 16
#define Dh 64
#define Mrows (Bb * Ss)   // 4096

// ---------------- scratch (device globals; no allocation allowed) ------------
__device__ float g_q[Mrows * Dd];
__device__ float g_k[Mrows * Dd];
__device__ float g_v[Mrows * Dd];
__device__ float g_h[Mrows * (Dd / 2)];
__device__ float g_att[Mrows * Dd];
__device__ float g_imp[Mrows];
__device__ int   g_topk[Bb * Kk];
__device__ unsigned char g_sel[Bb * Ss];

// ---------------- fp32 tiled GEMM: C[M,N] = A[M,Kd] @ W[Kd,N] + bias ---------
// BM=BN=128, BK=16, 256 threads, 8x8 register tile per thread.
__global__ __launch_bounds__(256) void sgemm_bias(
    const float* __restrict__ A, const float* __restrict__ W,
    const float* __restrict__ bias, float* __restrict__ C,
    int M, int N, int Kd, int relu)
{
    __shared__ float As[16][128];   // transposed A tile
    __shared__ float Bs[16][128];

    const int bx = blockIdx.x;      // N tile
    const int by = blockIdx.y;      // M tile
    const int tid = threadIdx.x;
    const int tcol = tid & 15;      // 0..15
    const int trow = tid >> 4;      // 0..15

    float acc[8][8];
#pragma unroll
    for (int i = 0; i < 8; i++)
#pragma unroll
        for (int j = 0; j < 8; j++) acc[i][j] = 0.f;

    const float* Ab = A + (size_t)by * 128 * Kd;
    const float* Wb = W + bx * 128;

    for (int k0 = 0; k0 < Kd; k0 += 16) {
        // Load A tile 128x16 (512 float4 slots, 2 per thread), store transposed
#pragma unroll
        for (int l = 0; l < 2; l++) {
            int lin = tid + l * 256;          // 0..511
            int row = lin >> 2;               // 0..127
            int c4  = lin & 3;                // 0..3
            float4 a = *(const float4*)(Ab + (size_t)row * Kd + k0 + c4 * 4);
            As[c4 * 4 + 0][row] = a.x;
            As[c4 * 4 + 1][row] = a.y;
            As[c4 * 4 + 2][row] = a.z;
            As[c4 * 4 + 3][row] = a.w;
        }
        // Load W tile 16x128 (512 float4 slots, 2 per thread)
#pragma unroll
        for (int l = 0; l < 2; l++) {
            int lin = tid + l * 256;
            int row = lin >> 5;               // 0..15
            int c4  = lin & 31;               // 0..31
            float4 b = *(const float4*)(Wb + (size_t)(k0 + row) * N + c4 * 4);
            *(float4*)(&Bs[row][c4 * 4]) = b;
        }
        __syncthreads();

#pragma unroll
        for (int k = 0; k < 16; k++) {
            float ra[8], rb[8];
#pragma unroll
            for (int i = 0; i < 8; i++) ra[i] = As[k][trow * 8 + i];
#pragma unroll
            for (int j = 0; j < 8; j++) rb[j] = Bs[k][tcol * 8 + j];
#pragma unroll
            for (int i = 0; i < 8; i++)
#pragma unroll
                for (int j = 0; j < 8; j++)
                    acc[i][j] = fmaf(ra[i], rb[j], acc[i][j]);
        }
        __syncthreads();
    }

#pragma unroll
    for (int i = 0; i < 8; i++) {
        int row = by * 128 + trow * 8 + i;
#pragma unroll
        for (int j = 0; j < 8; j++) {
            int col = bx * 128 + tcol * 8 + j;
            float v = acc[i][j] + bias[col];
            if (relu) v = fmaxf(v, 0.f);
            C[(size_t)row * N + col] = v;
        }
    }
}

// ---------------- importance logits: imp[r] = relu_h[r,:] . Ws2 + bs2 --------
__global__ __launch_bounds__(256) void imp_kernel(
    const float* __restrict__ Hm, const float* __restrict__ Ws2,
    const float* __restrict__ bs2, float* __restrict__ imp)
{
    int row  = blockIdx.x * 8 + (threadIdx.x >> 5);
    int lane = threadIdx.x & 31;
    const float* hr = Hm + (size_t)row * 512;
    float s = 0.f;
#pragma unroll 4
    for (int j = lane; j < 512; j += 32) s += hr[j] * Ws2[j];
#pragma unroll
    for (int o = 16; o > 0; o >>= 1) s += __shfl_xor_sync(0xffffffffu, s, o);
    if (lane == 0) imp[row] = s + bs2[0];
}

// ---------------- per-batch top-16 (argmax x16) ------------------------------
__global__ __launch_bounds__(256) void topk_kernel(
    const float* __restrict__ imp, int* __restrict__ topk,
    unsigned char* __restrict__ sel)
{
    __shared__ float vals[Ss];
    __shared__ float rmax[256];
    __shared__ int   ridx[256];
    int b = blockIdx.x, t = threadIdx.x;
    for (int j = t; j < Ss; j += 256) {
        vals[j] = imp[b * Ss + j];
        sel[b * Ss + j] = 0;
    }
    __syncthreads();
    for (int it = 0; it < Kk; it++) {
        float m = -INFINITY; int mi = 0;
        for (int j = t; j < Ss; j += 256) {
            float v = vals[j];
            if (v > m) { m = v; mi = j; }
        }
        rmax[t] = m; ridx[t] = mi;
        __syncthreads();
        for (int s2 = 128; s2 > 0; s2 >>= 1) {
            if (t < s2 && rmax[t + s2] > rmax[t]) {
                rmax[t] = rmax[t + s2]; ridx[t] = ridx[t + s2];
            }
            __syncthreads();
        }
        if (t == 0) {
            int mi0 = ridx[0];
            topk[b * Kk + it] = mi0;
            sel[b * Ss + mi0] = 1;
            vals[mi0] = -INFINITY;
        }
        __syncthreads();
    }
}

// ---------------- sparse rows: each query attends to the 16 selected keys ----
// One warp per (b,h,i); 4 warps per block.
__global__ __launch_bounds__(128) void attn_sparse(
    const float* __restrict__ q, const float* __restrict__ k,
    const float* __restrict__ v, const int* __restrict__ topk,
    const unsigned char* __restrict__ sel, float* __restrict__ att)
{
    int w = threadIdx.x >> 5, lane = threadIdx.x & 31;
    int qid = blockIdx.x * 4 + w;        // 0 .. B*H*S-1
    int b = qid >> 15;                   // / (H*S)=32768
    int rem = qid & 32767;
    int h = rem >> 11;                   // / S
    int i = rem & 2047;
    if (sel[b * Ss + i]) return;         // handled by dense kernel

    const float4* q4 = (const float4*)(q + ((size_t)(b * Ss + i) * Dd + h * Dh));
    float score = -INFINITY;
    int kj = 0;
    if (lane < 16) {
        kj = topk[b * Kk + lane];
        const float4* k4 = (const float4*)(k + ((size_t)(b * Ss + kj) * Dd + h * Dh));
        float s = 0.f;
#pragma unroll
        for (int d = 0; d < 16; d++) {
            float4 a = q4[d], c = k4[d];
            s += a.x * c.x + a.y * c.y + a.z * c.z + a.w * c.w;
        }
        score = s * 0.125f;
    }
    float m = score;
#pragma unroll
    for (int o = 16; o > 0; o >>= 1) m = fmaxf(m, __shfl_xor_sync(0xffffffffu, m, o));
    float e = (lane < 16) ? expf(score - m) : 0.f;
    float ssum = e;
#pragma unroll
    for (int o = 16; o > 0; o >>= 1) ssum += __shfl_xor_sync(0xffffffffu, ssum, o);
    float wgt = e / ssum;

    float acc0 = 0.f, acc1 = 0.f;
#pragma unroll
    for (int j = 0; j < 16; j++) {
        float wj = __shfl_sync(0xffffffffu, wgt, j);
        int kjj  = __shfl_sync(0xffffffffu, kj, j);
        const float* vp = v + ((size_t)(b * Ss + kjj) * Dd + h * Dh);
        acc0 = fmaf(wj, vp[lane], acc0);
        acc1 = fmaf(wj, vp[lane + 32], acc1);
    }
    float* op = att + ((size_t)(b * Ss + i) * Dd + h * Dh);
    op[lane] = acc0;
    op[lane + 32] = acc1;
}

// ---------------- dense rows: selected queries attend to all 2048 keys -------
// One block per (b, iq, h); 256 threads.
__global__ __launch_bounds__(256) void attn_dense(
    const float* __restrict__ q, const float* __restrict__ k,
    const float* __restrict__ v, const int* __restrict__ topk,
    float* __restrict__ att)
{
    __shared__ float sc[Ss];
    __shared__ float red[256];
    __shared__ float part[256];

    int bid = blockIdx.x;                // b*K*H
    int b = bid >> 8;                    // / (K*H)=256
    int rem = bid & 255;
    int iq = rem >> 4;
    int h  = rem & 15;
    int i  = topk[b * Kk + iq];
    int t  = threadIdx.x;

    const float4* q4 = (const float4*)(q + ((size_t)(b * Ss + i) * Dd + h * Dh));

    float lmax = -INFINITY;
    for (int j = t; j < Ss; j += 256) {
        const float4* k4 = (const float4*)(k + ((size_t)(b * Ss + j) * Dd + h * Dh));
        float s = 0.f;
#pragma unroll
        for (int d = 0; d < 16; d++) {
            float4 a = q4[d], c = k4[d];
            s += a.x * c.x + a.y * c.y + a.z * c.z + a.w * c.w;
        }
        s *= 0.125f;
        sc[j] = s;
        lmax = fmaxf(lmax, s);
    }
    red[t] = lmax;
    __syncthreads();
    for (int s2 = 128; s2 > 0; s2 >>= 1) {
        if (t < s2) red[t] = fmaxf(red[t], red[t + s2]);
        __syncthreads();
    }
    float m = red[0];
    __syncthreads();

    float lsum = 0.f;
    for (int j = t; j < Ss; j += 256) {
        float e = expf(sc[j] - m);
        sc[j] = e;
        lsum += e;
    }
    red[t] = lsum;
    __syncthreads();
    for (int s2 = 128; s2 > 0; s2 >>= 1) {
        if (t < s2) red[t] += red[t + s2];
        __syncthreads();
    }
    float inv = 1.f / red[0];
    __syncthreads();

    // weighted sum over V: thread t handles dim d=t&63, j-chunk t>>6
    int d = t & 63, chunk = t >> 6;
    float acc = 0.f;
    const float* vb = v + ((size_t)(b * Ss) * Dd + h * Dh + d);
    int j0 = chunk * 512;
#pragma unroll 4
    for (int j = j0; j < j0 + 512; j++) {
        acc = fmaf(sc[j], vb[(size_t)j * Dd], acc);
    }
    part[t] = acc;
    __syncthreads();
    if (t < 64) {
        float o = (part[t] + part[t + 64] + part[t + 128] + part[t + 192]) * inv;
        att[((size_t)(b * Ss + i) * Dd + h * Dh + d)] = o;
    }
}

// ---------------- launcher ---------------------------------------------------
extern "C" void kernel_launch(void* const* d_in, const int* in_sizes, int n_in,
                              void* d_out, int out_size)
{
    const float* x   = (const float*)d_in[0];
    const float* Wq  = (const float*)d_in[1];
    const float* bq  = (const float*)d_in[2];
    const float* Wk  = (const float*)d_in[3];
    const float* bk  = (const float*)d_in[4];
    const float* Wv  = (const float*)d_in[5];
    const float* bv  = (const float*)d_in[6];
    const float* Wo  = (const float*)d_in[7];
    const float* bo  = (const float*)d_in[8];
    const float* Ws1 = (const float*)d_in[9];
    const float* bs1 = (const float*)d_in[10];
    const float* Ws2 = (const float*)d_in[11];
    const float* bs2 = (const float*)d_in[12];
    float* out = (float*)d_out;

    float *q, *k, *v, *hbuf, *attb, *impb;
    int *tkb; unsigned char *selb;
    cudaGetSymbolAddress((void**)&q,    g_q);
    cudaGetSymbolAddress((void**)&k,    g_k);
    cudaGetSymbolAddress((void**)&v,    g_v);
    cudaGetSymbolAddress((void**)&hbuf, g_h);
    cudaGetSymbolAddress((void**)&attb, g_att);
    cudaGetSymbolAddress((void**)&impb, g_imp);
    cudaGetSymbolAddress((void**)&tkb,  g_topk);
    cudaGetSymbolAddress((void**)&selb, g_sel);

    dim3 gProj(Dd / 128, Mrows / 128);      // (8, 32)
    dim3 gHid((Dd / 2) / 128, Mrows / 128); // (4, 32)

    sgemm_bias<<<gProj, 256>>>(x, Wq, bq, q, Mrows, Dd, Dd, 0);
    sgemm_bias<<<gProj, 256>>>(x, Wk, bk, k, Mrows, Dd, Dd, 0);
    sgemm_bias<<<gProj, 256>>>(x, Wv, bv, v, Mrows, Dd, Dd, 0);
    sgemm_bias<<<gHid,  256>>>(x, Ws1, bs1, hbuf, Mrows, Dd / 2, Dd, 1);

    imp_kernel<<<Mrows / 8, 256>>>(hbuf, Ws2, bs2, impb);
    topk_kernel<<<Bb, 256>>>(impb, tkb, selb);

    attn_sparse<<<(Bb * Hh * Ss) / 4, 128>>>(q, k, v, tkb, selb, attb);
    attn_dense<<<Bb * Kk * Hh, 256>>>(q, k, v, tkb, attb);

    sgemm_bias<<<gProj, 256>>>(attb, Wo, bo, out, Mrows, Dd, Dd, 0);
}

// round 5
// speedup vs baseline: 2.1195x; 2.1195x over previous
#include <cuda_runtime.h>
#include <cuda_bf16.h>
#include <math.h>
#include <stdint.h>

// Problem constants
#define Bb 2
#define Ss 2048
#define Dd 1024
#define Hh 16
#define Kk 16
#define Dh 64
#define Mrows (Bb * Ss)   // 4096
#define K3 3072           // augmented K for bf16x3 split

// ---------------- scratch (device globals; no allocation allowed) ------------
__device__ float g_q[Mrows * Dd];
__device__ float g_k[Mrows * Dd];
__device__ float g_v[Mrows * Dd];
__device__ float g_h[Mrows * (Dd / 2)];
__device__ float g_att[Mrows * Dd];
__device__ float g_imp[Mrows];
__device__ int   g_topk[Bb * Kk];
__device__ unsigned char g_sel[Bb * Ss];

// bf16x3 split buffers
__device__ __nv_bfloat16 g_a3x[(size_t)Mrows * K3];
__device__ __nv_bfloat16 g_a3att[(size_t)Mrows * K3];
__device__ __nv_bfloat16 g_b3q[(size_t)Dd * K3];
__device__ __nv_bfloat16 g_b3k[(size_t)Dd * K3];
__device__ __nv_bfloat16 g_b3v[(size_t)Dd * K3];
__device__ __nv_bfloat16 g_b3o[(size_t)Dd * K3];
__device__ __nv_bfloat16 g_b3s1[(size_t)(Dd / 2) * K3];

// ================= helpers ===================================================
__device__ __forceinline__ uint32_t smem_to_u32(const void* p) {
    uint32_t a;
    asm("{ .reg .u64 t; cvta.to.shared.u64 t, %1; cvt.u32.u64 %0, t; }" : "=r"(a) : "l"(p));
    return a;
}
__device__ __forceinline__ void cp_async16(uint32_t dst, const void* src) {
    asm volatile("cp.async.cg.shared.global [%0], [%1], 16;" :: "r"(dst), "l"(src));
}
#define CP_COMMIT() asm volatile("cp.async.commit_group;" ::: "memory")
#define CP_WAIT(n)  asm volatile("cp.async.wait_group %0;" :: "n"(n) : "memory")

__device__ __forceinline__ void ldsm_x4(uint32_t* r, uint32_t addr) {
    asm volatile("ldmatrix.sync.aligned.m8n8.x4.shared.b16 {%0,%1,%2,%3}, [%4];"
        : "=r"(r[0]), "=r"(r[1]), "=r"(r[2]), "=r"(r[3]) : "r"(addr));
}
__device__ __forceinline__ void mma16816(float* d, const uint32_t* a, const uint32_t* b) {
    asm volatile(
        "mma.sync.aligned.m16n8k16.row.col.f32.bf16.bf16.f32 "
        "{%0,%1,%2,%3}, {%4,%5,%6,%7}, {%8,%9}, {%0,%1,%2,%3};"
        : "+f"(d[0]), "+f"(d[1]), "+f"(d[2]), "+f"(d[3])
        : "r"(a[0]), "r"(a[1]), "r"(a[2]), "r"(a[3]), "r"(b[0]), "r"(b[1]));
}

// ================= conversion kernels ========================================
// split_A: fp32 [M,1024] -> bf16 [M, 3072] laid out [hi | hi | lo]
__global__ __launch_bounds__(256) void splitA_kernel(
    const float* __restrict__ A, __nv_bfloat16* __restrict__ A3)
{
    int i = blockIdx.x * 256 + threadIdx.x;
    float a = A[i];
    __nv_bfloat16 hi = __float2bfloat16(a);
    float r = a - __bfloat162float(hi);
    __nv_bfloat16 lo = __float2bfloat16(r);
    int row = i >> 10, kcol = i & 1023;
    size_t base = (size_t)row * K3;
    A3[base + kcol]        = hi;
    A3[base + 1024 + kcol] = hi;
    A3[base + 2048 + kcol] = lo;
}

// split_W: fp32 W[1024, N] -> bf16 B3[N, 3072] K-major (B3[n][k] = split(W[k][n]))
// layout along K: [hi | lo | hi]   (A [hi|hi|lo] x B [hi|lo|hi] = hh + hl + lh)
__global__ __launch_bounds__(256) void splitW_kernel(
    const float* __restrict__ W, __nv_bfloat16* __restrict__ B3, int N)
{
    __shared__ float tile[32][33];
    int tx = threadIdx.x & 31, ty = threadIdx.x >> 5;  // 32x8
    int n0 = blockIdx.x * 32, k0 = blockIdx.y * 32;
#pragma unroll
    for (int j = 0; j < 32; j += 8)
        tile[ty + j][tx] = W[(size_t)(k0 + ty + j) * N + n0 + tx];
    __syncthreads();
#pragma unroll
    for (int j = 0; j < 32; j += 8) {
        int n = ty + j;
        float a = tile[tx][n];               // = W[k0+tx][n0+n]
        __nv_bfloat16 hi = __float2bfloat16(a);
        float r = a - __bfloat162float(hi);
        __nv_bfloat16 lo = __float2bfloat16(r);
        size_t base = (size_t)(n0 + n) * K3 + k0 + tx;
        B3[base]        = hi;
        B3[base + 1024] = lo;
        B3[base + 2048] = hi;
    }
}

// ================= tensor-core GEMM (mma.sync, bf16) =========================
// C[M,N] = A3[M,3072] . B3[N,3072]^T + bias, optional relu.
// CTA tile 128x128, BK=64 (128B rows, XOR swizzle), 256 threads (8 warps 4x2),
// per-warp 32x64 (2 M-frags x 8 N-frags), cp.async double buffering.
#define GT_SMEM_TOTAL 65536

__global__ __launch_bounds__(256) void gemm_tc(
    const __nv_bfloat16* __restrict__ A3, const __nv_bfloat16* __restrict__ B3,
    const float* __restrict__ bias, float* __restrict__ C, int N, int relu)
{
    extern __shared__ __align__(1024) char smem[];
    uint32_t sb = smem_to_u32(smem);
    int tid = threadIdx.x, lane = tid & 31, wid = tid >> 5;
    int wm = wid & 3, wn = wid >> 2;
    int bx = blockIdx.x, by = blockIdx.y;

    const __nv_bfloat16* Abp = A3 + (size_t)by * 128 * K3;
    const __nv_bfloat16* Bbp = B3 + (size_t)bx * 128 * K3;

    // per-thread global->smem copy geometry: 4 rows (r0 + l*32), fixed 16B col
    int r0  = tid >> 3;           // 0..31
    int c16 = tid & 7;            // 0..7
    uint32_t swoff[4];
#pragma unroll
    for (int l = 0; l < 4; l++) {
        uint32_t off = (r0 + l * 32) * 128 + c16 * 16;
        swoff[l] = off ^ ((off >> 3) & 0x70);
    }

    float acc[2][8][4];
#pragma unroll
    for (int mt = 0; mt < 2; mt++)
#pragma unroll
        for (int nt = 0; nt < 8; nt++)
#pragma unroll
            for (int c = 0; c < 4; c++) acc[mt][nt][c] = 0.f;

    // precompute ldmatrix smem offsets (within a 16KB tile buffer)
    uint32_t a_ld[2], b_ld[4];
#pragma unroll
    for (int mt = 0; mt < 2; mt++) {
        int row = wm * 32 + mt * 16 + ((lane >> 3) & 1) * 8 + (lane & 7);
        a_ld[mt] = (uint32_t)(row * 128 + (lane >> 4) * 16);
    }
#pragma unroll
    for (int p = 0; p < 4; p++) {
        int row = wn * 64 + p * 16 + (lane >> 4) * 8 + (lane & 7);
        b_ld[p] = (uint32_t)(row * 128 + ((lane >> 3) & 1) * 16);
    }

    // prologue: load iter 0 into buffer 0
    {
#pragma unroll
        for (int l = 0; l < 4; l++) {
            int row = r0 + l * 32;
            cp_async16(sb + swoff[l],         Abp + (size_t)row * K3 + c16 * 8);
            cp_async16(sb + 32768 + swoff[l], Bbp + (size_t)row * K3 + c16 * 8);
        }
        CP_COMMIT();
    }

#pragma unroll 1
    for (int it = 0; it < 48; ++it) {
        int buf = it & 1;
        if (it + 1 < 48) {
            const __nv_bfloat16* Ak = Abp + (it + 1) * 64;
            const __nv_bfloat16* Bk = Bbp + (it + 1) * 64;
            uint32_t abase = sb + (buf ^ 1) * 16384;
            uint32_t bbase = sb + 32768 + (buf ^ 1) * 16384;
#pragma unroll
            for (int l = 0; l < 4; l++) {
                int row = r0 + l * 32;
                cp_async16(abase + swoff[l], Ak + (size_t)row * K3 + c16 * 8);
                cp_async16(bbase + swoff[l], Bk + (size_t)row * K3 + c16 * 8);
            }
            CP_COMMIT();
            CP_WAIT(1);
        } else {
            CP_WAIT(0);
        }
        __syncthreads();

        uint32_t ab = sb + buf * 16384;
        uint32_t bbS = sb + 32768 + buf * 16384;
#pragma unroll
        for (int s = 0; s < 4; ++s) {
            uint32_t kb = s * 32;   // 16 k-elements = 32 bytes
            uint32_t afr[2][4];
#pragma unroll
            for (int mt = 0; mt < 2; mt++) {
                uint32_t off = a_ld[mt] + kb;
                ldsm_x4(afr[mt], ab + (off ^ ((off >> 3) & 0x70)));
            }
            uint32_t bfr[8][2];
#pragma unroll
            for (int p = 0; p < 4; p++) {
                uint32_t off = b_ld[p] + kb;
                uint32_t r[4];
                ldsm_x4(r, bbS + (off ^ ((off >> 3) & 0x70)));
                bfr[2 * p][0] = r[0]; bfr[2 * p][1] = r[1];
                bfr[2 * p + 1][0] = r[2]; bfr[2 * p + 1][1] = r[3];
            }
#pragma unroll
            for (int mt = 0; mt < 2; mt++)
#pragma unroll
                for (int nt = 0; nt < 8; nt++)
                    mma16816(acc[mt][nt], afr[mt], bfr[nt]);
        }
        __syncthreads();
    }

    // epilogue
    int g = lane >> 2, t4 = lane & 3;
#pragma unroll
    for (int mt = 0; mt < 2; mt++) {
        int row = by * 128 + wm * 32 + mt * 16 + g;
#pragma unroll
        for (int nt = 0; nt < 8; nt++) {
            int col = bx * 128 + wn * 64 + nt * 8 + t4 * 2;
            float b0 = bias[col], b1 = bias[col + 1];
            float v0 = acc[mt][nt][0] + b0;
            float v1 = acc[mt][nt][1] + b1;
            float v2 = acc[mt][nt][2] + b0;
            float v3 = acc[mt][nt][3] + b1;
            if (relu) {
                v0 = fmaxf(v0, 0.f); v1 = fmaxf(v1, 0.f);
                v2 = fmaxf(v2, 0.f); v3 = fmaxf(v3, 0.f);
            }
            *(float2*)(C + (size_t)row * N + col)       = make_float2(v0, v1);
            *(float2*)(C + (size_t)(row + 8) * N + col) = make_float2(v2, v3);
        }
    }
}

// ---------------- importance logits: imp[r] = relu_h[r,:] . Ws2 + bs2 --------
__global__ __launch_bounds__(256) void imp_kernel(
    const float* __restrict__ Hm, const float* __restrict__ Ws2,
    const float* __restrict__ bs2, float* __restrict__ imp)
{
    int row  = blockIdx.x * 8 + (threadIdx.x >> 5);
    int lane = threadIdx.x & 31;
    const float* hr = Hm + (size_t)row * 512;
    float s = 0.f;
#pragma unroll 4
    for (int j = lane; j < 512; j += 32) s += hr[j] * Ws2[j];
#pragma unroll
    for (int o = 16; o > 0; o >>= 1) s += __shfl_xor_sync(0xffffffffu, s, o);
    if (lane == 0) imp[row] = s + bs2[0];
}

// ---------------- per-batch top-16 (argmax x16) ------------------------------
__global__ __launch_bounds__(256) void topk_kernel(
    const float* __restrict__ imp, int* __restrict__ topk,
    unsigned char* __restrict__ sel)
{
    __shared__ float vals[Ss];
    __shared__ float rmax[256];
    __shared__ int   ridx[256];
    int b = blockIdx.x, t = threadIdx.x;
    for (int j = t; j < Ss; j += 256) {
        vals[j] = imp[b * Ss + j];
        sel[b * Ss + j] = 0;
    }
    __syncthreads();
    for (int it = 0; it < Kk; it++) {
        float m = -INFINITY; int mi = 0;
        for (int j = t; j < Ss; j += 256) {
            float v = vals[j];
            if (v > m) { m = v; mi = j; }
        }
        rmax[t] = m; ridx[t] = mi;
        __syncthreads();
        for (int s2 = 128; s2 > 0; s2 >>= 1) {
            if (t < s2 && rmax[t + s2] > rmax[t]) {
                rmax[t] = rmax[t + s2]; ridx[t] = ridx[t + s2];
            }
            __syncthreads();
        }
        if (t == 0) {
            int mi0 = ridx[0];
            topk[b * Kk + it] = mi0;
            sel[b * Ss + mi0] = 1;
            vals[mi0] = -INFINITY;
        }
        __syncthreads();
    }
}

// ---------------- sparse rows ------------------------------------------------
__global__ __launch_bounds__(128) void attn_sparse(
    const float* __restrict__ q, const float* __restrict__ k,
    const float* __restrict__ v, const int* __restrict__ topk,
    const unsigned char* __restrict__ sel, float* __restrict__ att)
{
    int w = threadIdx.x >> 5, lane = threadIdx.x & 31;
    int qid = blockIdx.x * 4 + w;
    int b = qid >> 15;
    int rem = qid & 32767;
    int h = rem >> 11;
    int i = rem & 2047;
    if (sel[b * Ss + i]) return;

    const float4* q4 = (const float4*)(q + ((size_t)(b * Ss + i) * Dd + h * Dh));
    float score = -INFINITY;
    int kj = 0;
    if (lane < 16) {
        kj = topk[b * Kk + lane];
        const float4* k4 = (const float4*)(k + ((size_t)(b * Ss + kj) * Dd + h * Dh));
        float s = 0.f;
#pragma unroll
        for (int d = 0; d < 16; d++) {
            float4 a = q4[d], c = k4[d];
            s += a.x * c.x + a.y * c.y + a.z * c.z + a.w * c.w;
        }
        score = s * 0.125f;
    }
    float m = score;
#pragma unroll
    for (int o = 16; o > 0; o >>= 1) m = fmaxf(m, __shfl_xor_sync(0xffffffffu, m, o));
    float e = (lane < 16) ? expf(score - m) : 0.f;
    float ssum = e;
#pragma unroll
    for (int o = 16; o > 0; o >>= 1) ssum += __shfl_xor_sync(0xffffffffu, ssum, o);
    float wgt = e / ssum;

    float acc0 = 0.f, acc1 = 0.f;
#pragma unroll
    for (int j = 0; j < 16; j++) {
        float wj = __shfl_sync(0xffffffffu, wgt, j);
        int kjj  = __shfl_sync(0xffffffffu, kj, j);
        const float* vp = v + ((size_t)(b * Ss + kjj) * Dd + h * Dh);
        acc0 = fmaf(wj, vp[lane], acc0);
        acc1 = fmaf(wj, vp[lane + 32], acc1);
    }
    float* op = att + ((size_t)(b * Ss + i) * Dd + h * Dh);
    op[lane] = acc0;
    op[lane + 32] = acc1;
}

// ---------------- dense rows -------------------------------------------------
__global__ __launch_bounds__(256) void attn_dense(
    const float* __restrict__ q, const float* __restrict__ k,
    const float* __restrict__ v, const int* __restrict__ topk,
    float* __restrict__ att)
{
    __shared__ float sc[Ss];
    __shared__ float red[256];
    __shared__ float part[256];

    int bid = blockIdx.x;
    int b = bid >> 8;
    int rem = bid & 255;
    int iq = rem >> 4;
    int h  = rem & 15;
    int i  = topk[b * Kk + iq];
    int t  = threadIdx.x;

    const float4* q4 = (const float4*)(q + ((size_t)(b * Ss + i) * Dd + h * Dh));

    float lmax = -INFINITY;
    for (int j = t; j < Ss; j += 256) {
        const float4* k4 = (const float4*)(k + ((size_t)(b * Ss + j) * Dd + h * Dh));
        float s = 0.f;
#pragma unroll
        for (int d = 0; d < 16; d++) {
            float4 a = q4[d], c = k4[d];
            s += a.x * c.x + a.y * c.y + a.z * c.z + a.w * c.w;
        }
        s *= 0.125f;
        sc[j] = s;
        lmax = fmaxf(lmax, s);
    }
    red[t] = lmax;
    __syncthreads();
    for (int s2 = 128; s2 > 0; s2 >>= 1) {
        if (t < s2) red[t] = fmaxf(red[t], red[t + s2]);
        __syncthreads();
    }
    float m = red[0];
    __syncthreads();

    float lsum = 0.f;
    for (int j = t; j < Ss; j += 256) {
        float e = expf(sc[j] - m);
        sc[j] = e;
        lsum += e;
    }
    red[t] = lsum;
    __syncthreads();
    for (int s2 = 128; s2 > 0; s2 >>= 1) {
        if (t < s2) red[t] += red[t + s2];
        __syncthreads();
    }
    float inv = 1.f / red[0];
    __syncthreads();

    int d = t & 63, chunk = t >> 6;
    float acc = 0.f;
    const float* vb = v + ((size_t)(b * Ss) * Dd + h * Dh + d);
    int j0 = chunk * 512;
#pragma unroll 4
    for (int j = j0; j < j0 + 512; j++) {
        acc = fmaf(sc[j], vb[(size_t)j * Dd], acc);
    }
    part[t] = acc;
    __syncthreads();
    if (t < 64) {
        float o = (part[t] + part[t + 64] + part[t + 128] + part[t + 192]) * inv;
        att[((size_t)(b * Ss + i) * Dd + h * Dh + d)] = o;
    }
}

// ---------------- launcher ---------------------------------------------------
extern "C" void kernel_launch(void* const* d_in, const int* in_sizes, int n_in,
                              void* d_out, int out_size)
{
    const float* x   = (const float*)d_in[0];
    const float* Wq  = (const float*)d_in[1];
    const float* bq  = (const float*)d_in[2];
    const float* Wk  = (const float*)d_in[3];
    const float* bk  = (const float*)d_in[4];
    const float* Wv  = (const float*)d_in[5];
    const float* bv  = (const float*)d_in[6];
    const float* Wo  = (const float*)d_in[7];
    const float* bo  = (const float*)d_in[8];
    const float* Ws1 = (const float*)d_in[9];
    const float* bs1 = (const float*)d_in[10];
    const float* Ws2 = (const float*)d_in[11];
    const float* bs2 = (const float*)d_in[12];
    float* out = (float*)d_out;

    float *q, *k, *v, *hbuf, *attb, *impb;
    int *tkb; unsigned char *selb;
    __nv_bfloat16 *a3x, *a3att, *b3q, *b3k, *b3v, *b3o, *b3s1;
    cudaGetSymbolAddress((void**)&q,     g_q);
    cudaGetSymbolAddress((void**)&k,     g_k);
    cudaGetSymbolAddress((void**)&v,     g_v);
    cudaGetSymbolAddress((void**)&hbuf,  g_h);
    cudaGetSymbolAddress((void**)&attb,  g_att);
    cudaGetSymbolAddress((void**)&impb,  g_imp);
    cudaGetSymbolAddress((void**)&tkb,   g_topk);
    cudaGetSymbolAddress((void**)&selb,  g_sel);
    cudaGetSymbolAddress((void**)&a3x,   g_a3x);
    cudaGetSymbolAddress((void**)&a3att, g_a3att);
    cudaGetSymbolAddress((void**)&b3q,   g_b3q);
    cudaGetSymbolAddress((void**)&b3k,   g_b3k);
    cudaGetSymbolAddress((void**)&b3v,   g_b3v);
    cudaGetSymbolAddress((void**)&b3o,   g_b3o);
    cudaGetSymbolAddress((void**)&b3s1,  g_b3s1);

    cudaFuncSetAttribute(gemm_tc, cudaFuncAttributeMaxDynamicSharedMemorySize,
                         GT_SMEM_TOTAL);

    // conversions
    splitA_kernel<<<(Mrows * Dd) / 256, 256>>>(x, a3x);
    splitW_kernel<<<dim3(Dd / 32, Dd / 32), 256>>>(Wq, b3q, Dd);
    splitW_kernel<<<dim3(Dd / 32, Dd / 32), 256>>>(Wk, b3k, Dd);
    splitW_kernel<<<dim3(Dd / 32, Dd / 32), 256>>>(Wv, b3v, Dd);
    splitW_kernel<<<dim3(Dd / 32, Dd / 32), 256>>>(Wo, b3o, Dd);
    splitW_kernel<<<dim3((Dd / 2) / 32, Dd / 32), 256>>>(Ws1, b3s1, Dd / 2);

    // tensor-core GEMMs
    dim3 gFull(Dd / 128, Mrows / 128);       // (8, 32)
    dim3 gHalf((Dd / 2) / 128, Mrows / 128); // (4, 32)
    gemm_tc<<<gFull, 256, GT_SMEM_TOTAL>>>(a3x, b3q, bq, q, Dd, 0);
    gemm_tc<<<gFull, 256, GT_SMEM_TOTAL>>>(a3x, b3k, bk, k, Dd, 0);
    gemm_tc<<<gFull, 256, GT_SMEM_TOTAL>>>(a3x, b3v, bv, v, Dd, 0);
    gemm_tc<<<gHalf, 256, GT_SMEM_TOTAL>>>(a3x, b3s1, bs1, hbuf, Dd / 2, 1);

    // indexer + attention
    imp_kernel<<<Mrows / 8, 256>>>(hbuf, Ws2, bs2, impb);
    topk_kernel<<<Bb, 256>>>(impb, tkb, selb);
    attn_sparse<<<(Bb * Hh * Ss) / 4, 128>>>(q, k, v, tkb, selb, attb);
    attn_dense<<<Bb * Kk * Hh, 256>>>(q, k, v, tkb, attb);

    // output projection
    splitA_kernel<<<(Mrows * Dd) / 256, 256>>>(attb, a3att);
    gemm_tc<<<gFull, 256, GT_SMEM_TOTAL>>>(a3att, b3o, bo, out, Dd, 0);
}

// round 6
// speedup vs baseline: 2.5774x; 1.2160x over previous
#include <cuda_runtime.h>
#include <cuda_fp16.h>
#include <math.h>
#include <stdint.h>

// Problem constants
#define Bb 2
#define Ss 2048
#define Dd 1024
#define Hh 16
#define Kk 16
#define Dh 64
#define Mrows (Bb * Ss)   // 4096
#define QKVN 3072         // concatenated q|k|v row width

// ---------------- scratch (device globals; no allocation allowed) ------------
__device__ float g_qkv[(size_t)Mrows * QKVN];   // q|k|v concatenated
__device__ float g_h[Mrows * (Dd / 2)];
__device__ float g_att[Mrows * Dd];
__device__ float g_imp[Mrows];
__device__ int   g_topk[Bb * Kk];
__device__ unsigned char g_sel[Bb * Ss];

// fp16 split buffers
__device__ __half g_a2x[(size_t)Mrows * 2048];     // x:  [hi | lo]
__device__ __half g_a2att[(size_t)Mrows * 2048];   // att:[hi | lo]
__device__ __half g_bqkv[(size_t)QKVN * 1024];     // Wq^T|Wk^T|Wv^T hi only
__device__ __half g_b2o[(size_t)Dd * 2048];        // Wo^T  [hi | lo]
__device__ __half g_b2s1[(size_t)(Dd / 2) * 2048]; // Ws1^T [hi | lo]

// ================= helpers ===================================================
__device__ __forceinline__ uint32_t smem_to_u32(const void* p) {
    uint32_t a;
    asm("{ .reg .u64 t; cvta.to.shared.u64 t, %1; cvt.u32.u64 %0, t; }" : "=r"(a) : "l"(p));
    return a;
}
__device__ __forceinline__ void cp_async16(uint32_t dst, const void* src) {
    asm volatile("cp.async.cg.shared.global [%0], [%1], 16;" :: "r"(dst), "l"(src));
}
#define CP_COMMIT() asm volatile("cp.async.commit_group;" ::: "memory")
#define CP_WAIT(n)  asm volatile("cp.async.wait_group %0;" :: "n"(n) : "memory")

__device__ __forceinline__ void ldsm_x4(uint32_t* r, uint32_t addr) {
    asm volatile("ldmatrix.sync.aligned.m8n8.x4.shared.b16 {%0,%1,%2,%3}, [%4];"
        : "=r"(r[0]), "=r"(r[1]), "=r"(r[2]), "=r"(r[3]) : "r"(addr));
}
__device__ __forceinline__ void mma16816(float* d, const uint32_t* a, const uint32_t* b) {
    asm volatile(
        "mma.sync.aligned.m16n8k16.row.col.f32.f16.f16.f32 "
        "{%0,%1,%2,%3}, {%4,%5,%6,%7}, {%8,%9}, {%0,%1,%2,%3};"
        : "+f"(d[0]), "+f"(d[1]), "+f"(d[2]), "+f"(d[3])
        : "r"(a[0]), "r"(a[1]), "r"(a[2]), "r"(a[3]), "r"(b[0]), "r"(b[1]));
}

// ================= conversion kernels ========================================
// fp32 [M,1024] -> fp16 [M, 2048] = [hi | lo]
__global__ __launch_bounds__(256) void splitA2_kernel(
    const float* __restrict__ A, __half* __restrict__ A2)
{
    int i = blockIdx.x * 256 + threadIdx.x;
    float a = A[i];
    __half hi = __float2half(a);
    __half lo = __float2half(a - __half2float(hi));
    int row = i >> 10, kcol = i & 1023;
    size_t base = (size_t)row * 2048;
    A2[base + kcol]        = hi;
    A2[base + 1024 + kcol] = lo;
}

// W[1024,N] fp32 -> Bo[N,1024] fp16 (hi only, transposed)
__global__ __launch_bounds__(256) void splitWh_kernel(
    const float* __restrict__ W, __half* __restrict__ Bo, int N)
{
    __shared__ float tile[32][33];
    int tx = threadIdx.x & 31, ty = threadIdx.x >> 5;
    int n0 = blockIdx.x * 32, k0 = blockIdx.y * 32;
#pragma unroll
    for (int j = 0; j < 32; j += 8)
        tile[ty + j][tx] = W[(size_t)(k0 + ty + j) * N + n0 + tx];
    __syncthreads();
#pragma unroll
    for (int j = 0; j < 32; j += 8) {
        int n = ty + j;
        float a = tile[tx][n];
        Bo[(size_t)(n0 + n) * 1024 + k0 + tx] = __float2half(a);
    }
}

// W[1024,N] fp32 -> Bo[N,2048] fp16 = [hi | lo] (transposed)
__global__ __launch_bounds__(256) void splitW2_kernel(
    const float* __restrict__ W, __half* __restrict__ Bo, int N)
{
    __shared__ float tile[32][33];
    int tx = threadIdx.x & 31, ty = threadIdx.x >> 5;
    int n0 = blockIdx.x * 32, k0 = blockIdx.y * 32;
#pragma unroll
    for (int j = 0; j < 32; j += 8)
        tile[ty + j][tx] = W[(size_t)(k0 + ty + j) * N + n0 + tx];
    __syncthreads();
#pragma unroll
    for (int j = 0; j < 32; j += 8) {
        int n = ty + j;
        float a = tile[tx][n];
        __half hi = __float2half(a);
        __half lo = __float2half(a - __half2float(hi));
        size_t base = (size_t)(n0 + n) * 2048 + k0 + tx;
        Bo[base]        = hi;
        Bo[base + 1024] = lo;
    }
}

// ================= tensor-core GEMM (mma.sync, fp16) =========================
// mode3=0 (QKV): iters=32, A segs [hi,lo], B seg always hi (ldB=1024);
//   computes (ah+al).bh = a.bh.
// mode3=1 (O/S1): iters=48, segs (a,b) = (0,0),(0,1),(1,0) over [hi|lo] buffers;
//   computes ah.bh + ah.bl + al.bh.
// CTA tile 128x128, BK=64 (128B rows, XOR swizzle), 256 threads, cp.async
// double buffering, per-warp 32x64.
#define GT_SMEM_TOTAL 65536

__global__ __launch_bounds__(256) void gemm_tc(
    const __half* __restrict__ A2, const __half* __restrict__ B2,
    const float* __restrict__ bias0, const float* __restrict__ bias1,
    const float* __restrict__ bias2, float* __restrict__ C,
    int ldB, int ldC, int iters, int mode3, int relu)
{
    extern __shared__ __align__(1024) char smem[];
    uint32_t sb = smem_to_u32(smem);
    int tid = threadIdx.x, lane = tid & 31, wid = tid >> 5;
    int wm = wid & 3, wn = wid >> 2;
    int bx = blockIdx.x, by = blockIdx.y;

    const __half* Abp = A2 + (size_t)by * 128 * 2048;
    const __half* Bbp = B2 + (size_t)bx * 128 * ldB;

    int r0  = tid >> 3;           // 0..31
    int c16 = tid & 7;            // 0..7
    uint32_t swoff[4];
#pragma unroll
    for (int l = 0; l < 4; l++) {
        uint32_t off = (r0 + l * 32) * 128 + c16 * 16;
        swoff[l] = off ^ ((off >> 3) & 0x70);
    }

    float acc[2][8][4];
#pragma unroll
    for (int mt = 0; mt < 2; mt++)
#pragma unroll
        for (int nt = 0; nt < 8; nt++)
#pragma unroll
            for (int c = 0; c < 4; c++) acc[mt][nt][c] = 0.f;

    uint32_t a_ld[2], b_ld[4];
#pragma unroll
    for (int mt = 0; mt < 2; mt++) {
        int row = wm * 32 + mt * 16 + ((lane >> 3) & 1) * 8 + (lane & 7);
        a_ld[mt] = (uint32_t)(row * 128 + (lane >> 4) * 16);
    }
#pragma unroll
    for (int p = 0; p < 4; p++) {
        int row = wn * 64 + p * 16 + (lane >> 4) * 8 + (lane & 7);
        b_ld[p] = (uint32_t)(row * 128 + ((lane >> 3) & 1) * 16);
    }

    // prologue: iter 0 (aoff=0, boff=0) into buffer 0
#pragma unroll
    for (int l = 0; l < 4; l++) {
        int row = r0 + l * 32;
        cp_async16(sb + swoff[l],         Abp + (size_t)row * 2048 + c16 * 8);
        cp_async16(sb + 32768 + swoff[l], Bbp + (size_t)row * ldB + c16 * 8);
    }
    CP_COMMIT();

#pragma unroll 1
    for (int it = 0; it < iters; ++it) {
        int buf = it & 1;
        if (it + 1 < iters) {
            int nx = it + 1;
            int kwithin = (nx & 15) * 64;
            int aoff, boff;
            if (!mode3) {
                aoff = (nx >> 4) * 1024 + kwithin;
                boff = kwithin;
            } else {
                int seg = nx >> 4;
                aoff = (seg == 2 ? 1024 : 0) + kwithin;
                boff = (seg == 1 ? 1024 : 0) + kwithin;
            }
            const __half* Ak = Abp + aoff;
            const __half* Bk = Bbp + boff;
            uint32_t abase = sb + (buf ^ 1) * 16384;
            uint32_t bbase = sb + 32768 + (buf ^ 1) * 16384;
#pragma unroll
            for (int l = 0; l < 4; l++) {
                int row = r0 + l * 32;
                cp_async16(abase + swoff[l], Ak + (size_t)row * 2048 + c16 * 8);
                cp_async16(bbase + swoff[l], Bk + (size_t)row * ldB + c16 * 8);
            }
            CP_COMMIT();
            CP_WAIT(1);
        } else {
            CP_WAIT(0);
        }
        __syncthreads();

        uint32_t ab = sb + buf * 16384;
        uint32_t bbS = sb + 32768 + buf * 16384;
#pragma unroll
        for (int s = 0; s < 4; ++s) {
            uint32_t kb = s * 32;
            uint32_t afr[2][4];
#pragma unroll
            for (int mt = 0; mt < 2; mt++) {
                uint32_t off = a_ld[mt] + kb;
                ldsm_x4(afr[mt], ab + (off ^ ((off >> 3) & 0x70)));
            }
            uint32_t bfr[8][2];
#pragma unroll
            for (int p = 0; p < 4; p++) {
                uint32_t off = b_ld[p] + kb;
                uint32_t r[4];
                ldsm_x4(r, bbS + (off ^ ((off >> 3) & 0x70)));
                bfr[2 * p][0] = r[0]; bfr[2 * p][1] = r[1];
                bfr[2 * p + 1][0] = r[2]; bfr[2 * p + 1][1] = r[3];
            }
#pragma unroll
            for (int mt = 0; mt < 2; mt++)
#pragma unroll
                for (int nt = 0; nt < 8; nt++)
                    mma16816(acc[mt][nt], afr[mt], bfr[nt]);
        }
        __syncthreads();
    }

    // epilogue: bias pointer by 1024-col segment (QKV: bx>>3 in {0,1,2})
    int bsel = bx >> 3;
    const float* bp = (bsel == 0) ? bias0 : (bsel == 1 ? bias1 : bias2);
    int bcol0 = (bx & 7) * 128;

    int g = lane >> 2, t4 = lane & 3;
#pragma unroll
    for (int mt = 0; mt < 2; mt++) {
        int row = by * 128 + wm * 32 + mt * 16 + g;
#pragma unroll
        for (int nt = 0; nt < 8; nt++) {
            int coff = wn * 64 + nt * 8 + t4 * 2;
            int col = bx * 128 + coff;
            float b0 = bp[bcol0 + coff], b1 = bp[bcol0 + coff + 1];
            float v0 = acc[mt][nt][0] + b0;
            float v1 = acc[mt][nt][1] + b1;
            float v2 = acc[mt][nt][2] + b0;
            float v3 = acc[mt][nt][3] + b1;
            if (relu) {
                v0 = fmaxf(v0, 0.f); v1 = fmaxf(v1, 0.f);
                v2 = fmaxf(v2, 0.f); v3 = fmaxf(v3, 0.f);
            }
            *(float2*)(C + (size_t)row * ldC + col)       = make_float2(v0, v1);
            *(float2*)(C + (size_t)(row + 8) * ldC + col) = make_float2(v2, v3);
        }
    }
}

// ---------------- importance logits: imp[r] = relu_h[r,:] . Ws2 + bs2 --------
__global__ __launch_bounds__(256) void imp_kernel(
    const float* __restrict__ Hm, const float* __restrict__ Ws2,
    const float* __restrict__ bs2, float* __restrict__ imp)
{
    int row  = blockIdx.x * 8 + (threadIdx.x >> 5);
    int lane = threadIdx.x & 31;
    const float* hr = Hm + (size_t)row * 512;
    float s = 0.f;
#pragma unroll 4
    for (int j = lane; j < 512; j += 32) s += hr[j] * Ws2[j];
#pragma unroll
    for (int o = 16; o > 0; o >>= 1) s += __shfl_xor_sync(0xffffffffu, s, o);
    if (lane == 0) imp[row] = s + bs2[0];
}

// ---------------- per-batch top-16: one warp per batch -----------------------
__global__ __launch_bounds__(32) void topk_kernel(
    const float* __restrict__ imp, int* __restrict__ topk,
    unsigned char* __restrict__ sel)
{
    __shared__ float vals[Ss];
    int b = blockIdx.x, lane = threadIdx.x;
    for (int j = lane; j < Ss; j += 32) {
        vals[j] = imp[b * Ss + j];
        sel[b * Ss + j] = 0;
    }
    __syncwarp();
    for (int it = 0; it < Kk; it++) {
        float m = -INFINITY; int mi = 0;
        for (int j = lane; j < Ss; j += 32) {
            float v = vals[j];
            if (v > m) { m = v; mi = j; }
        }
#pragma unroll
        for (int o = 16; o > 0; o >>= 1) {
            float om = __shfl_xor_sync(0xffffffffu, m, o);
            int   oi = __shfl_xor_sync(0xffffffffu, mi, o);
            if (om > m) { m = om; mi = oi; }
        }
        mi = __shfl_sync(0xffffffffu, mi, 0);
        if (lane == 0) {
            topk[b * Kk + it] = mi;
            sel[b * Ss + mi] = 1;
        }
        vals[mi] = -INFINITY;
        __syncwarp();
    }
}

// ---------------- sparse rows (qkv concatenated, stride 3072) ----------------
__global__ __launch_bounds__(128) void attn_sparse(
    const float* __restrict__ qkv, const int* __restrict__ topk,
    const unsigned char* __restrict__ sel, float* __restrict__ att)
{
    int w = threadIdx.x >> 5, lane = threadIdx.x & 31;
    int qid = blockIdx.x * 4 + w;
    int b = qid >> 15;
    int rem = qid & 32767;
    int h = rem >> 11;
    int i = rem & 2047;
    if (sel[b * Ss + i]) return;

    const float4* q4 = (const float4*)(qkv + ((size_t)(b * Ss + i) * QKVN + h * Dh));
    float score = -INFINITY;
    int kj = 0;
    if (lane < 16) {
        kj = topk[b * Kk + lane];
        const float4* k4 = (const float4*)(qkv + ((size_t)(b * Ss + kj) * QKVN + 1024 + h * Dh));
        float s = 0.f;
#pragma unroll
        for (int d = 0; d < 16; d++) {
            float4 a = q4[d], c = k4[d];
            s += a.x * c.x + a.y * c.y + a.z * c.z + a.w * c.w;
        }
        score = s * 0.125f;
    }
    float m = score;
#pragma unroll
    for (int o = 16; o > 0; o >>= 1) m = fmaxf(m, __shfl_xor_sync(0xffffffffu, m, o));
    float e = (lane < 16) ? expf(score - m) : 0.f;
    float ssum = e;
#pragma unroll
    for (int o = 16; o > 0; o >>= 1) ssum += __shfl_xor_sync(0xffffffffu, ssum, o);
    float wgt = e / ssum;

    float acc0 = 0.f, acc1 = 0.f;
#pragma unroll
    for (int j = 0; j < 16; j++) {
        float wj = __shfl_sync(0xffffffffu, wgt, j);
        int kjj  = __shfl_sync(0xffffffffu, kj, j);
        const float* vp = qkv + ((size_t)(b * Ss + kjj) * QKVN + 2048 + h * Dh);
        acc0 = fmaf(wj, vp[lane], acc0);
        acc1 = fmaf(wj, vp[lane + 32], acc1);
    }
    float* op = att + ((size_t)(b * Ss + i) * Dd + h * Dh);
    op[lane] = acc0;
    op[lane + 32] = acc1;
}

// ---------------- dense rows -------------------------------------------------
__global__ __launch_bounds__(256) void attn_dense(
    const float* __restrict__ qkv, const int* __restrict__ topk,
    float* __restrict__ att)
{
    __shared__ float sc[Ss];
    __shared__ float red[256];
    __shared__ float part[256];

    int bid = blockIdx.x;
    int b = bid >> 8;
    int rem = bid & 255;
    int iq = rem >> 4;
    int h  = rem & 15;
    int i  = topk[b * Kk + iq];
    int t  = threadIdx.x;

    const float4* q4 = (const float4*)(qkv + ((size_t)(b * Ss + i) * QKVN + h * Dh));

    float lmax = -INFINITY;
    for (int j = t; j < Ss; j += 256) {
        const float4* k4 = (const float4*)(qkv + ((size_t)(b * Ss + j) * QKVN + 1024 + h * Dh));
        float s = 0.f;
#pragma unroll
        for (int d = 0; d < 16; d++) {
            float4 a = q4[d], c = k4[d];
            s += a.x * c.x + a.y * c.y + a.z * c.z + a.w * c.w;
        }
        s *= 0.125f;
        sc[j] = s;
        lmax = fmaxf(lmax, s);
    }
    red[t] = lmax;
    __syncthreads();
    for (int s2 = 128; s2 > 0; s2 >>= 1) {
        if (t < s2) red[t] = fmaxf(red[t], red[t + s2]);
        __syncthreads();
    }
    float m = red[0];
    __syncthreads();

    float lsum = 0.f;
    for (int j = t; j < Ss; j += 256) {
        float e = expf(sc[j] - m);
        sc[j] = e;
        lsum += e;
    }
    red[t] = lsum;
    __syncthreads();
    for (int s2 = 128; s2 > 0; s2 >>= 1) {
        if (t < s2) red[t] += red[t + s2];
        __syncthreads();
    }
    float inv = 1.f / red[0];
    __syncthreads();

    int d = t & 63, chunk = t >> 6;
    float acc = 0.f;
    const float* vb = qkv + ((size_t)(b * Ss) * QKVN + 2048 + h * Dh + d);
    int j0 = chunk * 512;
#pragma unroll 8
    for (int j = j0; j < j0 + 512; j++) {
        acc = fmaf(sc[j], vb[(size_t)j * QKVN], acc);
    }
    part[t] = acc;
    __syncthreads();
    if (t < 64) {
        float o = (part[t] + part[t + 64] + part[t + 128] + part[t + 192]) * inv;
        att[((size_t)(b * Ss + i) * Dd + h * Dh + d)] = o;
    }
}

// ---------------- launcher ---------------------------------------------------
extern "C" void kernel_launch(void* const* d_in, const int* in_sizes, int n_in,
                              void* d_out, int out_size)
{
    const float* x   = (const float*)d_in[0];
    const float* Wq  = (const float*)d_in[1];
    const float* bq  = (const float*)d_in[2];
    const float* Wk  = (const float*)d_in[3];
    const float* bk  = (const float*)d_in[4];
    const float* Wv  = (const float*)d_in[5];
    const float* bv  = (const float*)d_in[6];
    const float* Wo  = (const float*)d_in[7];
    const float* bo  = (const float*)d_in[8];
    const float* Ws1 = (const float*)d_in[9];
    const float* bs1 = (const float*)d_in[10];
    const float* Ws2 = (const float*)d_in[11];
    const float* bs2 = (const float*)d_in[12];
    float* out = (float*)d_out;

    float *qkv, *hbuf, *attb, *impb;
    int *tkb; unsigned char *selb;
    __half *a2x, *a2att, *bqkv, *b2o, *b2s1;
    cudaGetSymbolAddress((void**)&qkv,   g_qkv);
    cudaGetSymbolAddress((void**)&hbuf,  g_h);
    cudaGetSymbolAddress((void**)&attb,  g_att);
    cudaGetSymbolAddress((void**)&impb,  g_imp);
    cudaGetSymbolAddress((void**)&tkb,   g_topk);
    cudaGetSymbolAddress((void**)&selb,  g_sel);
    cudaGetSymbolAddress((void**)&a2x,   g_a2x);
    cudaGetSymbolAddress((void**)&a2att, g_a2att);
    cudaGetSymbolAddress((void**)&bqkv,  g_bqkv);
    cudaGetSymbolAddress((void**)&b2o,   g_b2o);
    cudaGetSymbolAddress((void**)&b2s1,  g_b2s1);

    cudaFuncSetAttribute(gemm_tc, cudaFuncAttributeMaxDynamicSharedMemorySize,
                         GT_SMEM_TOTAL);

    // conversions
    splitA2_kernel<<<(Mrows * Dd) / 256, 256>>>(x, a2x);
    splitWh_kernel<<<dim3(Dd / 32, Dd / 32), 256>>>(Wq, bqkv, Dd);
    splitWh_kernel<<<dim3(Dd / 32, Dd / 32), 256>>>(Wk, bqkv + (size_t)1024 * 1024, Dd);
    splitWh_kernel<<<dim3(Dd / 32, Dd / 32), 256>>>(Wv, bqkv + (size_t)2048 * 1024, Dd);
    splitW2_kernel<<<dim3(Dd / 32, Dd / 32), 256>>>(Wo, b2o, Dd);
    splitW2_kernel<<<dim3((Dd / 2) / 32, Dd / 32), 256>>>(Ws1, b2s1, Dd / 2);

    // fused QKV GEMM: [4096,2048]x[3072,1024] -> qkv [4096,3072]
    gemm_tc<<<dim3(QKVN / 128, Mrows / 128), 256, GT_SMEM_TOTAL>>>(
        a2x, bqkv, bq, bk, bv, qkv, 1024, QKVN, 32, 0, 0);
    // S1 GEMM (3-chunk): -> hbuf [4096,512], relu
    gemm_tc<<<dim3((Dd / 2) / 128, Mrows / 128), 256, GT_SMEM_TOTAL>>>(
        a2x, b2s1, bs1, bs1, bs1, hbuf, 2048, Dd / 2, 48, 1, 1);

    // indexer + attention
    imp_kernel<<<Mrows / 8, 256>>>(hbuf, Ws2, bs2, impb);
    topk_kernel<<<Bb, 32>>>(impb, tkb, selb);
    attn_sparse<<<(Bb * Hh * Ss) / 4, 128>>>(qkv, tkb, selb, attb);
    attn_dense<<<Bb * Kk * Hh, 256>>>(qkv, tkb, attb);

    // output projection (3-chunk)
    splitA2_kernel<<<(Mrows * Dd) / 256, 256>>>(attb, a2att);
    gemm_tc<<<dim3(Dd / 128, Mrows / 128), 256, GT_SMEM_TOTAL>>>(
        a2att, b2o, bo, bo, bo, out, 2048, Dd, 48, 1, 0);
}

// round 7
// speedup vs baseline: 3.4846x; 1.3520x over previous
#include <cuda_runtime.h>
#include <cuda_fp16.h>
#include <math.h>
#include <stdint.h>

// Problem constants
#define Bb 2
#define Ss 2048
#define Dd 1024
#define Hh 16
#define Kk 16
#define Dh 64
#define Mrows (Bb * Ss)   // 4096
#define QKVN 3072         // concatenated q|k|v row width

// ---------------- scratch (device globals; no allocation allowed) ------------
__device__ float g_qkv[(size_t)Mrows * QKVN];   // q|k|v concatenated fp32
__device__ float g_h[Mrows * (Dd / 2)];
__device__ float g_imp[Mrows];
__device__ int   g_topk[Bb * Kk];
__device__ unsigned char g_sel[Bb * Ss];

// fp16 split buffers
__device__ __half g_a2x[(size_t)Mrows * 2048];     // x:   [hi | lo]
__device__ __half g_a2att[(size_t)Mrows * 2048];   // att: [hi | lo] (written by attention)
__device__ __half g_bqkv[(size_t)QKVN * 1024];     // Wq^T|Wk^T|Wv^T hi only
__device__ __half g_boh[(size_t)Dd * 1024];        // Wo^T hi only
__device__ __half g_b2s1[(size_t)(Dd / 2) * 2048]; // Ws1^T [hi | lo]

// ================= helpers ===================================================
__device__ __forceinline__ uint32_t smem_to_u32(const void* p) {
    uint32_t a;
    asm("{ .reg .u64 t; cvta.to.shared.u64 t, %1; cvt.u32.u64 %0, t; }" : "=r"(a) : "l"(p));
    return a;
}
__device__ __forceinline__ void cp_async16(uint32_t dst, const void* src) {
    asm volatile("cp.async.cg.shared.global [%0], [%1], 16;" :: "r"(dst), "l"(src));
}
#define CP_COMMIT() asm volatile("cp.async.commit_group;" ::: "memory")
#define CP_WAIT(n)  asm volatile("cp.async.wait_group %0;" :: "n"(n) : "memory")

__device__ __forceinline__ void ldsm_x4(uint32_t* r, uint32_t addr) {
    asm volatile("ldmatrix.sync.aligned.m8n8.x4.shared.b16 {%0,%1,%2,%3}, [%4];"
        : "=r"(r[0]), "=r"(r[1]), "=r"(r[2]), "=r"(r[3]) : "r"(addr));
}
__device__ __forceinline__ void mma16816(float* d, const uint32_t* a, const uint32_t* b) {
    asm volatile(
        "mma.sync.aligned.m16n8k16.row.col.f32.f16.f16.f32 "
        "{%0,%1,%2,%3}, {%4,%5,%6,%7}, {%8,%9}, {%0,%1,%2,%3};"
        : "+f"(d[0]), "+f"(d[1]), "+f"(d[2]), "+f"(d[3])
        : "r"(a[0]), "r"(a[1]), "r"(a[2]), "r"(a[3]), "r"(b[0]), "r"(b[1]));
}

// ================= conversion kernels ========================================
// fp32 [M,1024] -> fp16 [M, 2048] = [hi | lo]
__global__ __launch_bounds__(256) void splitA2_kernel(
    const float* __restrict__ A, __half* __restrict__ A2)
{
    int i = blockIdx.x * 256 + threadIdx.x;
    float a = A[i];
    __half hi = __float2half(a);
    __half lo = __float2half(a - __half2float(hi));
    int row = i >> 10, kcol = i & 1023;
    size_t base = (size_t)row * 2048;
    A2[base + kcol]        = hi;
    A2[base + 1024 + kcol] = lo;
}

// W[1024,N] fp32 -> Bo[N,1024] fp16 (hi only, transposed)
__global__ __launch_bounds__(256) void splitWh_kernel(
    const float* __restrict__ W, __half* __restrict__ Bo, int N)
{
    __shared__ float tile[32][33];
    int tx = threadIdx.x & 31, ty = threadIdx.x >> 5;
    int n0 = blockIdx.x * 32, k0 = blockIdx.y * 32;
#pragma unroll
    for (int j = 0; j < 32; j += 8)
        tile[ty + j][tx] = W[(size_t)(k0 + ty + j) * N + n0 + tx];
    __syncthreads();
#pragma unroll
    for (int j = 0; j < 32; j += 8) {
        int n = ty + j;
        Bo[(size_t)(n0 + n) * 1024 + k0 + tx] = __float2half(tile[tx][n]);
    }
}

// W[1024,N] fp32 -> Bo[N,2048] fp16 = [hi | lo] (transposed)
__global__ __launch_bounds__(256) void splitW2_kernel(
    const float* __restrict__ W, __half* __restrict__ Bo, int N)
{
    __shared__ float tile[32][33];
    int tx = threadIdx.x & 31, ty = threadIdx.x >> 5;
    int n0 = blockIdx.x * 32, k0 = blockIdx.y * 32;
#pragma unroll
    for (int j = 0; j < 32; j += 8)
        tile[ty + j][tx] = W[(size_t)(k0 + ty + j) * N + n0 + tx];
    __syncthreads();
#pragma unroll
    for (int j = 0; j < 32; j += 8) {
        int n = ty + j;
        float a = tile[tx][n];
        __half hi = __float2half(a);
        __half lo = __float2half(a - __half2float(hi));
        size_t base = (size_t)(n0 + n) * 2048 + k0 + tx;
        Bo[base]        = hi;
        Bo[base + 1024] = lo;
    }
}

// ================= tensor-core GEMM (mma.sync, fp16) =========================
// mode 0 (QKV hi-only): iters=16, aoff=boff=k
// mode 1 (3-chunk):     iters=48, segs (a,b)=(0,0),(0,1),(1,0) over [hi|lo]
// mode 2 (2-chunk A):   iters=32, aoff=seg*1024+k, boff=k (exact A x Bhi)
// CTA tile 128x128, BK=64, XOR swizzle, 256 threads, cp.async double buffer.
#define GT_SMEM_TOTAL 65536

__global__ __launch_bounds__(256) void gemm_tc(
    const __half* __restrict__ A2, const __half* __restrict__ B2,
    const float* __restrict__ bias0, const float* __restrict__ bias1,
    const float* __restrict__ bias2, float* __restrict__ C,
    int ldA, int ldB, int ldC, int iters, int mode, int relu)
{
    extern __shared__ __align__(1024) char smem[];
    uint32_t sb = smem_to_u32(smem);
    int tid = threadIdx.x, lane = tid & 31, wid = tid >> 5;
    int wm = wid & 3, wn = wid >> 2;
    int bx = blockIdx.x, by = blockIdx.y;

    const __half* Abp = A2 + (size_t)by * 128 * ldA;
    const __half* Bbp = B2 + (size_t)bx * 128 * ldB;

    int r0  = tid >> 3;           // 0..31
    int c16 = tid & 7;            // 0..7
    uint32_t swoff[4];
#pragma unroll
    for (int l = 0; l < 4; l++) {
        uint32_t off = (r0 + l * 32) * 128 + c16 * 16;
        swoff[l] = off ^ ((off >> 3) & 0x70);
    }

    float acc[2][8][4];
#pragma unroll
    for (int mt = 0; mt < 2; mt++)
#pragma unroll
        for (int nt = 0; nt < 8; nt++)
#pragma unroll
            for (int c = 0; c < 4; c++) acc[mt][nt][c] = 0.f;

    uint32_t a_ld[2], b_ld[4];
#pragma unroll
    for (int mt = 0; mt < 2; mt++) {
        int row = wm * 32 + mt * 16 + ((lane >> 3) & 1) * 8 + (lane & 7);
        a_ld[mt] = (uint32_t)(row * 128 + (lane >> 4) * 16);
    }
#pragma unroll
    for (int p = 0; p < 4; p++) {
        int row = wn * 64 + p * 16 + (lane >> 4) * 8 + (lane & 7);
        b_ld[p] = (uint32_t)(row * 128 + ((lane >> 3) & 1) * 16);
    }

    // prologue: iter 0 (aoff=0, boff=0) into buffer 0
#pragma unroll
    for (int l = 0; l < 4; l++) {
        int row = r0 + l * 32;
        cp_async16(sb + swoff[l],         Abp + (size_t)row * ldA + c16 * 8);
        cp_async16(sb + 32768 + swoff[l], Bbp + (size_t)row * ldB + c16 * 8);
    }
    CP_COMMIT();

#pragma unroll 1
    for (int it = 0; it < iters; ++it) {
        int buf = it & 1;
        if (it + 1 < iters) {
            int nx = it + 1;
            int kwithin = (nx & 15) * 64;
            int aoff, boff;
            if (mode == 0) { aoff = kwithin; boff = kwithin; }
            else if (mode == 1) {
                int seg = nx >> 4;
                aoff = (seg == 2 ? 1024 : 0) + kwithin;
                boff = (seg == 1 ? 1024 : 0) + kwithin;
            } else {
                aoff = (nx >> 4) * 1024 + kwithin;
                boff = kwithin;
            }
            const __half* Ak = Abp + aoff;
            const __half* Bk = Bbp + boff;
            uint32_t abase = sb + (buf ^ 1) * 16384;
            uint32_t bbase = sb + 32768 + (buf ^ 1) * 16384;
#pragma unroll
            for (int l = 0; l < 4; l++) {
                int row = r0 + l * 32;
                cp_async16(abase + swoff[l], Ak + (size_t)row * ldA + c16 * 8);
                cp_async16(bbase + swoff[l], Bk + (size_t)row * ldB + c16 * 8);
            }
            CP_COMMIT();
            CP_WAIT(1);
        } else {
            CP_WAIT(0);
        }
        __syncthreads();

        uint32_t ab = sb + buf * 16384;
        uint32_t bbS = sb + 32768 + buf * 16384;
#pragma unroll
        for (int s = 0; s < 4; ++s) {
            uint32_t kb = s * 32;
            uint32_t afr[2][4];
#pragma unroll
            for (int mt = 0; mt < 2; mt++) {
                uint32_t off = a_ld[mt] + kb;
                ldsm_x4(afr[mt], ab + (off ^ ((off >> 3) & 0x70)));
            }
            uint32_t bfr[8][2];
#pragma unroll
            for (int p = 0; p < 4; p++) {
                uint32_t off = b_ld[p] + kb;
                uint32_t r[4];
                ldsm_x4(r, bbS + (off ^ ((off >> 3) & 0x70)));
                bfr[2 * p][0] = r[0]; bfr[2 * p][1] = r[1];
                bfr[2 * p + 1][0] = r[2]; bfr[2 * p + 1][1] = r[3];
            }
#pragma unroll
            for (int mt = 0; mt < 2; mt++)
#pragma unroll
                for (int nt = 0; nt < 8; nt++)
                    mma16816(acc[mt][nt], afr[mt], bfr[nt]);
        }
        __syncthreads();
    }

    // epilogue: bias pointer by 1024-col segment (QKV: bx>>3 in {0,1,2})
    int bsel = bx >> 3;
    const float* bp = (bsel == 0) ? bias0 : (bsel == 1 ? bias1 : bias2);
    int bcol0 = (bx & 7) * 128;

    int g = lane >> 2, t4 = lane & 3;
#pragma unroll
    for (int mt = 0; mt < 2; mt++) {
        int row = by * 128 + wm * 32 + mt * 16 + g;
#pragma unroll
        for (int nt = 0; nt < 8; nt++) {
            int coff = wn * 64 + nt * 8 + t4 * 2;
            int col = bx * 128 + coff;
            float b0 = bp[bcol0 + coff], b1 = bp[bcol0 + coff + 1];
            float v0 = acc[mt][nt][0] + b0;
            float v1 = acc[mt][nt][1] + b1;
            float v2 = acc[mt][nt][2] + b0;
            float v3 = acc[mt][nt][3] + b1;
            if (relu) {
                v0 = fmaxf(v0, 0.f); v1 = fmaxf(v1, 0.f);
                v2 = fmaxf(v2, 0.f); v3 = fmaxf(v3, 0.f);
            }
            *(float2*)(C + (size_t)row * ldC + col)       = make_float2(v0, v1);
            *(float2*)(C + (size_t)(row + 8) * ldC + col) = make_float2(v2, v3);
        }
    }
}

// ---------------- importance logits ------------------------------------------
__global__ __launch_bounds__(256) void imp_kernel(
    const float* __restrict__ Hm, const float* __restrict__ Ws2,
    const float* __restrict__ bs2, float* __restrict__ imp)
{
    int row  = blockIdx.x * 8 + (threadIdx.x >> 5);
    int lane = threadIdx.x & 31;
    const float* hr = Hm + (size_t)row * 512;
    float s = 0.f;
#pragma unroll 4
    for (int j = lane; j < 512; j += 32) s += hr[j] * Ws2[j];
#pragma unroll
    for (int o = 16; o > 0; o >>= 1) s += __shfl_xor_sync(0xffffffffu, s, o);
    if (lane == 0) imp[row] = s + bs2[0];
}

// ---------------- per-batch top-16: one warp per batch -----------------------
__global__ __launch_bounds__(32) void topk_kernel(
    const float* __restrict__ imp, int* __restrict__ topk,
    unsigned char* __restrict__ sel)
{
    __shared__ float vals[Ss];
    int b = blockIdx.x, lane = threadIdx.x;
    for (int j = lane; j < Ss; j += 32) {
        vals[j] = imp[b * Ss + j];
        sel[b * Ss + j] = 0;
    }
    __syncwarp();
    for (int it = 0; it < Kk; it++) {
        float m = -INFINITY; int mi = 0;
        for (int j = lane; j < Ss; j += 32) {
            float v = vals[j];
            if (v > m) { m = v; mi = j; }
        }
#pragma unroll
        for (int o = 16; o > 0; o >>= 1) {
            float om = __shfl_xor_sync(0xffffffffu, m, o);
            int   oi = __shfl_xor_sync(0xffffffffu, mi, o);
            if (om > m) { m = om; mi = oi; }
        }
        mi = __shfl_sync(0xffffffffu, mi, 0);
        if (lane == 0) {
            topk[b * Kk + it] = mi;
            sel[b * Ss + mi] = 1;
        }
        vals[mi] = -INFINITY;
        __syncwarp();
    }
}

// ---------------- sparse rows: 8 queries/block, kv+q staged in smem ----------
// writes fp16 hi/lo split directly into a2att
__global__ __launch_bounds__(256) void attn_sparse(
    const float* __restrict__ qkv, const int* __restrict__ topk,
    const unsigned char* __restrict__ sel, __half* __restrict__ a2att)
{
    __shared__ float k16[16 * 68];
    __shared__ float v16[16 * 68];
    __shared__ float qsm[8 * 64];

    int tid = threadIdx.x, w = tid >> 5, lane = tid & 31;
    int qid0 = blockIdx.x * 8;
    int b = qid0 >> 15;
    int rem = qid0 & 32767;
    int h = rem >> 11;
    int i0 = rem & 2047;
    int i = i0 + w;

    // stage the 16 selected k/v rows
    {
        int key = tid >> 4;            // 0..15
        int d0  = (tid & 15) * 4;      // 0..60
        int kj = topk[b * Kk + key];
        const float* kr = qkv + (size_t)(b * Ss + kj) * QKVN + 1024 + h * Dh + d0;
        const float* vr = kr + 1024;
        float4 kv = *(const float4*)kr;
        k16[key * 68 + d0 + 0] = kv.x; k16[key * 68 + d0 + 1] = kv.y;
        k16[key * 68 + d0 + 2] = kv.z; k16[key * 68 + d0 + 3] = kv.w;
        float4 vv = *(const float4*)vr;
        v16[key * 68 + d0 + 0] = vv.x; v16[key * 68 + d0 + 1] = vv.y;
        v16[key * 68 + d0 + 2] = vv.z; v16[key * 68 + d0 + 3] = vv.w;
    }
    // stage this warp's q row
    {
        const float* qr = qkv + (size_t)(b * Ss + i) * QKVN + h * Dh;
        qsm[w * 64 + lane]      = qr[lane];
        qsm[w * 64 + lane + 32] = qr[lane + 32];
    }
    __syncthreads();

    if (sel[b * Ss + i]) return;   // dense kernel handles selected rows

    float score = -INFINITY;
    if (lane < 16) {
        float s = 0.f;
#pragma unroll
        for (int d = 0; d < 64; d++) s += qsm[w * 64 + d] * k16[lane * 68 + d];
        score = s * 0.125f;
    }
    float m = score;
#pragma unroll
    for (int o = 16; o > 0; o >>= 1) m = fmaxf(m, __shfl_xor_sync(0xffffffffu, m, o));
    float e = (lane < 16) ? expf(score - m) : 0.f;
    float ssum = e;
#pragma unroll
    for (int o = 16; o > 0; o >>= 1) ssum += __shfl_xor_sync(0xffffffffu, ssum, o);
    float wgt = e / ssum;

    float acc0 = 0.f, acc1 = 0.f;
#pragma unroll
    for (int j = 0; j < 16; j++) {
        float wj = __shfl_sync(0xffffffffu, wgt, j);
        acc0 = fmaf(wj, v16[j * 68 + lane],      acc0);
        acc1 = fmaf(wj, v16[j * 68 + lane + 32], acc1);
    }
    size_t base = (size_t)(b * Ss + i) * 2048 + h * Dh;
    __half h0 = __float2half(acc0);
    __half h1 = __float2half(acc1);
    a2att[base + lane]             = h0;
    a2att[base + lane + 32]        = h1;
    a2att[base + 1024 + lane]      = __float2half(acc0 - __half2float(h0));
    a2att[base + 1024 + lane + 32] = __float2half(acc1 - __half2float(h1));
}

// ---------------- dense rows: flash-style, one block per (b,h) ---------------
// 512 threads = 16 warps, warp w owns dense query topk[b*16+w].
// K/V tiles of 128 keys staged in smem, shared by all warps.
#define AD_QS   0
#define AD_KS   4096                   // 64 x 132 floats
#define AD_VS   (4096 + 33792)         // 128 x 64 floats
#define AD_WS   (4096 + 33792 + 32768) // 16 x 128 floats
#define AD_SMEM (4096 + 33792 + 32768 + 8192)   // 78848

__global__ __launch_bounds__(512) void attn_dense(
    const float* __restrict__ qkv, const int* __restrict__ topk,
    __half* __restrict__ a2att)
{
    extern __shared__ __align__(16) char smraw[];
    float* qs = (float*)(smraw + AD_QS);
    float* ks = (float*)(smraw + AD_KS);
    float* vs = (float*)(smraw + AD_VS);
    float* ws = (float*)(smraw + AD_WS);

    int tid = threadIdx.x, w = tid >> 5, lane = tid & 31;
    int b = blockIdx.x >> 4, h = blockIdx.x & 15;
    int i = topk[b * Kk + w];

    {
        const float* qr = qkv + (size_t)(b * Ss + i) * QKVN + h * Dh;
        qs[w * 64 + lane]      = qr[lane];
        qs[w * 64 + lane + 32] = qr[lane + 32];
    }

    float m_run = -INFINITY, sum_l = 0.f, acc0 = 0.f, acc1 = 0.f;

#pragma unroll 1
    for (int t = 0; t < 16; ++t) {
        __syncthreads();
        // load 128 keys of K (transposed) and V
        {
            int key = tid >> 2;            // 0..127
            int d0  = (tid & 3) * 16;      // 0,16,32,48
            const float* kr = qkv + (size_t)(b * Ss + t * 128 + key) * QKVN + 1024 + h * Dh + d0;
            const float* vr = kr + 1024;
#pragma unroll
            for (int u = 0; u < 4; u++) {
                float4 kv = *(const float4*)(kr + u * 4);
                int d = d0 + u * 4;
                ks[(d + 0) * 132 + key] = kv.x;
                ks[(d + 1) * 132 + key] = kv.y;
                ks[(d + 2) * 132 + key] = kv.z;
                ks[(d + 3) * 132 + key] = kv.w;
                *(float4*)(vs + key * 64 + d) = *(const float4*)(vr + u * 4);
            }
        }
        __syncthreads();

        // scores: 4 keys per lane
        float sc4[4];
        float mloc = -INFINITY;
#pragma unroll
        for (int c = 0; c < 4; c++) {
            int kk = lane + c * 32;
            float s = 0.f;
#pragma unroll
            for (int d = 0; d < 64; d++) s += qs[w * 64 + d] * ks[d * 132 + kk];
            s *= 0.125f;
            sc4[c] = s;
            mloc = fmaxf(mloc, s);
        }
#pragma unroll
        for (int o = 16; o > 0; o >>= 1)
            mloc = fmaxf(mloc, __shfl_xor_sync(0xffffffffu, mloc, o));
        float m_new = fmaxf(m_run, mloc);
        float scale = expf(m_run - m_new);
        acc0 *= scale; acc1 *= scale; sum_l *= scale;
#pragma unroll
        for (int c = 0; c < 4; c++) {
            float wv = expf(sc4[c] - m_new);
            ws[w * 128 + lane + c * 32] = wv;
            sum_l += wv;
        }
        m_run = m_new;
        __syncwarp();
#pragma unroll 4
        for (int j = 0; j < 128; j++) {
            float wj = ws[w * 128 + j];
            acc0 = fmaf(wj, vs[j * 64 + lane],      acc0);
            acc1 = fmaf(wj, vs[j * 64 + lane + 32], acc1);
        }
    }

    float sum = sum_l;
#pragma unroll
    for (int o = 16; o > 0; o >>= 1) sum += __shfl_xor_sync(0xffffffffu, sum, o);
    float inv = 1.f / sum;
    float o0 = acc0 * inv, o1 = acc1 * inv;

    size_t base = (size_t)(b * Ss + i) * 2048 + h * Dh;
    __half h0 = __float2half(o0);
    __half h1 = __float2half(o1);
    a2att[base + lane]             = h0;
    a2att[base + lane + 32]        = h1;
    a2att[base + 1024 + lane]      = __float2half(o0 - __half2float(h0));
    a2att[base + 1024 + lane + 32] = __float2half(o1 - __half2float(h1));
}

// ---------------- launcher ---------------------------------------------------
extern "C" void kernel_launch(void* const* d_in, const int* in_sizes, int n_in,
                              void* d_out, int out_size)
{
    const float* x   = (const float*)d_in[0];
    const float* Wq  = (const float*)d_in[1];
    const float* bq  = (const float*)d_in[2];
    const float* Wk  = (const float*)d_in[3];
    const float* bk  = (const float*)d_in[4];
    const float* Wv  = (const float*)d_in[5];
    const float* bv  = (const float*)d_in[6];
    const float* Wo  = (const float*)d_in[7];
    const float* bo  = (const float*)d_in[8];
    const float* Ws1 = (const float*)d_in[9];
    const float* bs1 = (const float*)d_in[10];
    const float* Ws2 = (const float*)d_in[11];
    const float* bs2 = (const float*)d_in[12];
    float* out = (float*)d_out;

    float *qkv, *hbuf, *impb;
    int *tkb; unsigned char *selb;
    __half *a2x, *a2att, *bqkv, *boh, *b2s1;
    cudaGetSymbolAddress((void**)&qkv,   g_qkv);
    cudaGetSymbolAddress((void**)&hbuf,  g_h);
    cudaGetSymbolAddress((void**)&impb,  g_imp);
    cudaGetSymbolAddress((void**)&tkb,   g_topk);
    cudaGetSymbolAddress((void**)&selb,  g_sel);
    cudaGetSymbolAddress((void**)&a2x,   g_a2x);
    cudaGetSymbolAddress((void**)&a2att, g_a2att);
    cudaGetSymbolAddress((void**)&bqkv,  g_bqkv);
    cudaGetSymbolAddress((void**)&boh,   g_boh);
    cudaGetSymbolAddress((void**)&b2s1,  g_b2s1);

    cudaFuncSetAttribute(gemm_tc, cudaFuncAttributeMaxDynamicSharedMemorySize,
                         GT_SMEM_TOTAL);
    cudaFuncSetAttribute(attn_dense, cudaFuncAttributeMaxDynamicSharedMemorySize,
                         AD_SMEM);

    // conversions
    splitA2_kernel<<<(Mrows * Dd) / 256, 256>>>(x, a2x);
    splitWh_kernel<<<dim3(Dd / 32, Dd / 32), 256>>>(Wq, bqkv, Dd);
    splitWh_kernel<<<dim3(Dd / 32, Dd / 32), 256>>>(Wk, bqkv + (size_t)1024 * 1024, Dd);
    splitWh_kernel<<<dim3(Dd / 32, Dd / 32), 256>>>(Wv, bqkv + (size_t)2048 * 1024, Dd);
    splitWh_kernel<<<dim3(Dd / 32, Dd / 32), 256>>>(Wo, boh, Dd);
    splitW2_kernel<<<dim3((Dd / 2) / 32, Dd / 32), 256>>>(Ws1, b2s1, Dd / 2);

    // QKV hi-only GEMM: [4096,1024]x[3072,1024] -> qkv [4096,3072]
    gemm_tc<<<dim3(QKVN / 128, Mrows / 128), 256, GT_SMEM_TOTAL>>>(
        a2x, bqkv, bq, bk, bv, qkv, 2048, 1024, QKVN, 16, 0, 0);
    // S1 GEMM (3-chunk): -> hbuf [4096,512], relu
    gemm_tc<<<dim3((Dd / 2) / 128, Mrows / 128), 256, GT_SMEM_TOTAL>>>(
        a2x, b2s1, bs1, bs1, bs1, hbuf, 2048, 2048, Dd / 2, 48, 1, 1);

    // indexer + attention
    imp_kernel<<<Mrows / 8, 256>>>(hbuf, Ws2, bs2, impb);
    topk_kernel<<<Bb, 32>>>(impb, tkb, selb);
    attn_sparse<<<(Bb * Hh * Ss) / 8, 256>>>(qkv, tkb, selb, a2att);
    attn_dense<<<Bb * Hh, 512, AD_SMEM>>>(qkv, tkb, a2att);

    // output projection (2-chunk: exact att x Wo_hi)
    gemm_tc<<<dim3(Dd / 128, Mrows / 128), 256, GT_SMEM_TOTAL>>>(
        a2att, boh, bo, bo, bo, out, 2048, 1024, Dd, 32, 2, 0);
}